// round 16
// baseline (speedup 1.0000x reference)
#include <cuda_runtime.h>
#include <cuda_bf16.h>
#include <math.h>
#include <stdint.h>

// Problem constants
#define B 2
#define C 128
#define H 128
#define W 128
#define HP 130
#define WP 130
#define NPT 9
#define CO 128
#define BHW (B * H * W)

// Scratch (device globals; allocation-free)
__device__ __align__(16) float g_xp[B * HP * WP * C];           // padded NHWC x (~17.3 MB)
__device__ __align__(16) float4 g_gates2[NPT * BHW];            // gates [n][pix] (lt,rb,lb,rt)
__device__ __align__(16) int4   g_offs2 [NPT * BHW];            // corner spatial offsets [n][pix]
// Weights pre-packed PER MMA FRAGMENT (uint4 = lane's 4 a-regs, bf16x2 each):
//   main conv:   ((chunk*8 + m16)*4 + ks)*32 + lane   (chunk = tap*2 + half)
//   offset conv: ((chunk*2 + m16)*4 + ks)*32 + lane
__device__ __align__(16) uint4 g_wAf_hi[18 * 8 * 4 * 32];
__device__ __align__(16) uint4 g_wAf_lo[18 * 8 * 4 * 32];
__device__ __align__(16) uint4 g_wOf_hi[18 * 2 * 4 * 32];
__device__ __align__(16) uint4 g_wOf_lo[18 * 2 * 4 * 32];

// ---------------------------------------------------------------------------
// PTX helpers (all sm_80-era: no arch-"a" gated instructions)
__device__ __forceinline__ uint32_t smem_u32(const void* p) {
    uint32_t a;
    asm("{ .reg .u64 t; cvta.to.shared.u64 t, %1; cvt.u32.u64 %0, t; }" : "=r"(a) : "l"(p));
    return a;
}
__device__ __forceinline__ void ldmx4(uint32_t* r, uint32_t a) {
    asm volatile("ldmatrix.sync.aligned.m8n8.x4.shared.b16 {%0,%1,%2,%3}, [%4];"
                 : "=r"(r[0]), "=r"(r[1]), "=r"(r[2]), "=r"(r[3]) : "r"(a));
}
__device__ __forceinline__ void mma_bf16(float* c, const uint32_t* a, uint32_t b0, uint32_t b1) {
    asm volatile(
        "mma.sync.aligned.m16n8k16.row.col.f32.bf16.bf16.f32 "
        "{%0,%1,%2,%3}, {%4,%5,%6,%7}, {%8,%9}, {%0,%1,%2,%3};"
        : "+f"(c[0]), "+f"(c[1]), "+f"(c[2]), "+f"(c[3])
        : "r"(a[0]), "r"(a[1]), "r"(a[2]), "r"(a[3]), "r"(b0), "r"(b1));
}
__device__ __forceinline__ void bf16_split(float v, uint16_t& hi, uint16_t& lo) {
    __nv_bfloat16 h = __float2bfloat16_rn(v);
    __nv_bfloat16 l = __float2bfloat16_rn(v - __bfloat162float(h));
    hi = __bfloat16_as_ushort(h);
    lo = __bfloat16_as_ushort(l);
}
__device__ __forceinline__ uint32_t pack2(uint16_t a, uint16_t b) {
    return (uint32_t)a | ((uint32_t)b << 16);
}

// ---------------------------------------------------------------------------
// Kernel 0: zero only the pad border of g_xp (interior fully overwritten)
__global__ void zero_border_kernel() {
    int i = blockIdx.x * blockDim.x + threadIdx.x;
    if (i >= B * 516 * 32) return;
    int q = i & 31;
    int p = i >> 5;
    int b = p / 516;
    int r = p - b * 516;
    int hh, ww;
    if (r < 130)      { hh = 0;        ww = r; }
    else if (r < 260) { hh = 129;      ww = r - 130; }
    else if (r < 388) { hh = r - 259;  ww = 0; }
    else              { hh = r - 387;  ww = 129; }
    reinterpret_cast<float4*>(g_xp)[((size_t)(b * HP + hh) * WP + ww) * 32 + q] =
        make_float4(0.f, 0.f, 0.f, 0.f);
}

// ---------------------------------------------------------------------------
// Kernel 1: weight re-layouts -> per-fragment packed uint4 (main + offset conv)
__global__ void prep_weights_kernel(const float* __restrict__ wp,
                                    const float* __restrict__ wm,
                                    const float* __restrict__ wc) {
    const int n_of  = 18 * 2 * 4 * 32;       // 4608 offset-conv fragments
    const int n_wa  = 18 * 8 * 4 * 32;       // 18432 main-conv fragments
    for (int e = blockIdx.x * blockDim.x + threadIdx.x; e < n_of + n_wa;
         e += gridDim.x * blockDim.x) {
        if (e < n_of) {
            int chunk = e >> 8;               // tap*2 + half
            int r = e & 255;
            int m16 = r >> 7;
            int r2 = r & 127;
            int ks = r2 >> 5;
            int lane = r2 & 31;
            int g4 = lane >> 2, t4 = lane & 3;
            int tap = chunk >> 1, half = chunk & 1;
            uint32_t hi4[4], lo4[4];
#pragma unroll
            for (int j = 0; j < 4; ++j) {
                int ch = m16 * 16 + g4 + (j & 1) * 8;
                int kk = ks * 16 + t4 * 2 + (j >> 1) * 8;
                int ci = half * 64 + kk;
                float v0 = 0.f, v1 = 0.f;
                if (ch < 18) {
                    v0 = wp[(ch * C + ci) * 9 + tap];
                    v1 = wp[(ch * C + ci + 1) * 9 + tap];
                } else if (ch < 27) {
                    v0 = wm[((ch - 18) * C + ci) * 9 + tap];
                    v1 = wm[((ch - 18) * C + ci + 1) * 9 + tap];
                }
                uint16_t h0, l0, h1, l1;
                bf16_split(v0, h0, l0);
                bf16_split(v1, h1, l1);
                hi4[j] = pack2(h0, h1);
                lo4[j] = pack2(l0, l1);
            }
            g_wOf_hi[e] = make_uint4(hi4[0], hi4[1], hi4[2], hi4[3]);
            g_wOf_lo[e] = make_uint4(lo4[0], lo4[1], lo4[2], lo4[3]);
        } else {
            int t = e - n_of;                 // ((chunk*8+m16)*4+ks)*32+lane
            int chunk = t >> 10;
            int r = t & 1023;
            int m16 = r >> 7;
            int r2 = r & 127;
            int ks = r2 >> 5;
            int lane = r2 & 31;
            int g4 = lane >> 2, t4 = lane & 3;
            int tap = chunk >> 1, half = chunk & 1;
            uint32_t hi4[4], lo4[4];
#pragma unroll
            for (int j = 0; j < 4; ++j) {
                int row = m16 * 16 + g4 + (j & 1) * 8;           // co
                int kk  = ks * 16 + t4 * 2 + (j >> 1) * 8;       // k within chunk
                int ci = half * 64 + kk;
                float v0 = wc[(row * C + ci) * 9 + tap];
                float v1 = wc[(row * C + ci + 1) * 9 + tap];
                uint16_t h0, l0, h1, l1;
                bf16_split(v0, h0, l0);
                bf16_split(v1, h1, l1);
                hi4[j] = pack2(h0, h1);
                lo4[j] = pack2(l0, l1);
            }
            g_wAf_hi[t] = make_uint4(hi4[0], hi4[1], hi4[2], hi4[3]);
            g_wAf_lo[t] = make_uint4(lo4[0], lo4[1], lo4[2], lo4[3]);
        }
    }
}

// ---------------------------------------------------------------------------
// Kernel 2: pad + transpose NCHW -> padded NHWC
__global__ void pad_transpose_kernel(const float* __restrict__ x) {
    __shared__ float tile[32][33];
    int w0 = blockIdx.x * 32;
    int c0 = blockIdx.y * 32;
    int bh = blockIdx.z;
    int b = bh >> 7, h = bh & 127;
    int tx = threadIdx.x, ty = threadIdx.y;
#pragma unroll
    for (int r = 0; r < 4; ++r) {
        int ci = c0 + ty + r * 8;
        tile[ty + r * 8][tx] = x[(((size_t)b * C + ci) * H + h) * W + w0 + tx];
    }
    __syncthreads();
#pragma unroll
    for (int r = 0; r < 4; ++r) {
        int w = w0 + ty + r * 8;
        g_xp[(((size_t)b * HP + h + 1) * WP + (w + 1)) * C + c0 + tx] = tile[tx][ty + r * 8];
    }
}

// ---------------------------------------------------------------------------
// Kernel 3: offset/mask conv via HMMA, A-fragments direct from L2 (no W smem).
// Per ci-half: stage U once (tap-shift layout), then 9 taps x 4 k-steps with
// ZERO barriers. 4 barriers per CTA total. FUSED gate/index epilogue.
// CTA = 27(32) ch x 64 pixels, 256 thr, 3 CTAs/SM (57 KB smem).
#define SC_UROW (66 * 144)              // 9504 B per xp row
#define SC_UHI 0                        // 3 rows hi: 28512
#define SC_ULO (3 * SC_UROW)            // 3 rows lo: 28512
#define SC_TOTAL (6 * SC_UROW)          // 57024 B
__global__ __launch_bounds__(256, 3) void conv_mma_kernel(const float* __restrict__ bp,
                                                          const float* __restrict__ bm) {
    extern __shared__ __align__(128) char smem[];
    uint32_t sb = smem_u32(smem);
    int tid = threadIdx.x;
    int wid = tid >> 5, lane = tid & 31;

    int idx = blockIdx.x;
    int b = idx >> 8;
    int h = (idx >> 1) & 127;
    int w0 = (idx & 1) * 64;

    const float4* xb4 = reinterpret_cast<const float4*>(g_xp) + (size_t)b * HP * WP * 32;

    int wm = (wid & 1) * 16;          // ch half (m16 tile)
    int wn = (wid >> 1) * 16;         // pixel quarter

    int bRow = wn + ((lane >> 4) << 3) + (lane & 7);
    uint32_t bKoff = (uint32_t)(((lane >> 3) & 1) << 4);

    // A fragment table base for this warp's m16 tile
    const uint4* wOh0 = g_wOf_hi + (size_t)(wid & 1) * 128 + lane;
    const uint4* wOl0 = g_wOf_lo + (size_t)(wid & 1) * 128 + lane;

    float acc[2][4];
#pragma unroll
    for (int nt = 0; nt < 2; ++nt)
#pragma unroll
        for (int j = 0; j < 4; ++j) acc[nt][j] = 0.f;

    for (int half = 0; half < 2; ++half) {
        __syncthreads();   // previous half's MMAs done; U reusable

        // stage U: 3 rows x 66 pixels x 16 float4, hi/lo split
        for (int i = tid; i < 3 * 66 * 16; i += 256) {
            int row = i / (66 * 16);
            int rem = i - row * (66 * 16);
            int pix = rem >> 4;
            int q = rem & 15;
            float4 v = xb4[((size_t)(h + row) * WP + (w0 + pix)) * 32 + half * 16 + q];
            uint16_t hx, lx, hy, ly, hz, lz, hw_, lw_;
            bf16_split(v.x, hx, lx);
            bf16_split(v.y, hy, ly);
            bf16_split(v.z, hz, lz);
            bf16_split(v.w, hw_, lw_);
            uint32_t uoff = (uint32_t)(row * SC_UROW + pix * 144 + q * 8);
            *reinterpret_cast<uint2*>(smem + SC_UHI + uoff) = make_uint2(pack2(hx, hy), pack2(hz, hw_));
            *reinterpret_cast<uint2*>(smem + SC_ULO + uoff) = make_uint2(pack2(lx, ly), pack2(lz, lw_));
        }
        __syncthreads();

        // 9 taps x 4 k-steps, no barriers; A fragments from L2
#pragma unroll
        for (int tap = 0; tap < 9; ++tap) {
            int dh = tap / 3, dw = tap - dh * 3;
            int chunk = tap * 2 + half;
            const uint4* wOh = wOh0 + (size_t)chunk * 256;
            const uint4* wOl = wOl0 + (size_t)chunk * 256;
            uint32_t ubase = (uint32_t)(dh * SC_UROW) + (uint32_t)(bRow + dw) * 144 + bKoff;
#pragma unroll
            for (int ks = 0; ks < 4; ++ks) {
                uint4 ah4 = wOh[ks * 32];
                uint4 al4 = wOl[ks * 32];
                uint32_t AH[4] = {ah4.x, ah4.y, ah4.z, ah4.w};
                uint32_t AL[4] = {al4.x, al4.y, al4.z, al4.w};
                uint32_t bo = ubase + (uint32_t)(ks * 32);
                uint32_t BH[4], BL[4];
                ldmx4(BH, sb + SC_UHI + bo);
                ldmx4(BL, sb + SC_ULO + bo);
                mma_bf16(acc[0], AH, BH[0], BH[1]);
                mma_bf16(acc[0], AL, BH[0], BH[1]);
                mma_bf16(acc[0], AH, BL[0], BL[1]);
                mma_bf16(acc[1], AH, BH[2], BH[3]);
                mma_bf16(acc[1], AL, BH[2], BH[3]);
                mma_bf16(acc[1], AH, BL[2], BL[3]);
            }
        }
    }

    // ---- fused epilogue: exchange acc through smem, compute gates/offs ----
    __syncthreads();
    float* sacc = reinterpret_cast<float*>(smem);   // [32 ch][64 pix]
    {
        int g4 = lane >> 2, t4 = lane & 3;
#pragma unroll
        for (int nt = 0; nt < 2; ++nt) {
            int px = wn + nt * 8 + t4 * 2;
            int ch = wm + g4;
            *reinterpret_cast<float2*>(&sacc[ch * 64 + px]) = make_float2(acc[nt][0], acc[nt][1]);
            *reinterpret_cast<float2*>(&sacc[(ch + 8) * 64 + px]) = make_float2(acc[nt][2], acc[nt][3]);
        }
    }
    __syncthreads();

    int gpix0 = (b * H + h) * W + w0;
    for (int i = tid; i < 64 * NPT; i += 256) {
        int pix = i & 63;
        int n = i >> 6;
        float ox = sacc[n * 64 + pix]        + bp[n];
        float oy = sacc[(9 + n) * 64 + pix]  + bp[9 + n];
        float mr = sacc[(18 + n) * 64 + pix] + bm[n];
        float m = 1.f / (1.f + expf(-mr));
        float px = ox + (float)(h + 1) + (float)(n / 3 - 1);
        float py = oy + (float)(w0 + pix + 1) + (float)(n % 3 - 1);
        float fx = floorf(px), fy = floorf(py);
        float qltx = fminf(fmaxf(fx,       0.f), 129.f);
        float qlty = fminf(fmaxf(fy,       0.f), 129.f);
        float qrbx = fminf(fmaxf(fx + 1.f, 0.f), 129.f);
        float qrby = fminf(fmaxf(fy + 1.f, 0.f), 129.f);
        float pxc = fminf(fmaxf(px, 0.f), 129.f);
        float pyc = fminf(fmaxf(py, 0.f), 129.f);
        float ax = 1.f + (qltx - pxc);
        float bx = 1.f - (qrbx - pxc);
        float ay = 1.f + (qlty - pyc);
        float by = 1.f - (qrby - pyc);
        int ilt_x = (int)qltx, ilt_y = (int)qlty;
        int irb_x = (int)qrbx, irb_y = (int)qrby;
        g_gates2[n * BHW + gpix0 + pix] = make_float4(ax * ay * m, bx * by * m, ax * by * m, bx * ay * m);
        g_offs2 [n * BHW + gpix0 + pix] = make_int4(ilt_x * WP + ilt_y, irb_x * WP + irb_y,
                                                    ilt_x * WP + irb_y, irb_x * WP + ilt_y);
    }
}

// ---------------------------------------------------------------------------
// Kernel 4: fused gather + bf16-split GEMM; A-fragments direct from L2.
// CTA = 128 co x 128 pixels, 256 thr (8 warps, 2M x 4N), 2 CTAs/SM.
// K = 1152 as 18 chunks of 64. U double-buffered (73.7 KB); ONE barrier/chunk.
#define SMU0 0
#define SMU1 36864
#define UPLANE 18432                  // lo plane offset within a U buffer
#define SM_TOTAL 73728

__device__ __forceinline__ void gather_chunk(char* udst, int chunk, int gbase,
                                             const float4* xb4, int gp, int lq) {
    int tap = chunk >> 1, half = chunk & 1;
    const float4* xh = xb4 + half * 16;
    const float4* gg = g_gates2 + (size_t)tap * BHW + gbase;
    const int4*  go = g_offs2  + (size_t)tap * BHW + gbase;
#pragma unroll
    for (int pp = 0; pp < 8; ++pp) {
        int pix = gp + pp * 2;
        float4 g = gg[pix];
        int4  o = go[pix];
        float4 v0 = xh[(size_t)o.x * 32 + lq];
        float4 v1 = xh[(size_t)o.y * 32 + lq];
        float4 v2 = xh[(size_t)o.z * 32 + lq];
        float4 v3 = xh[(size_t)o.w * 32 + lq];
        float4 v;
        v.x = fmaf(g.w, v3.x, fmaf(g.z, v2.x, fmaf(g.y, v1.x, g.x * v0.x)));
        v.y = fmaf(g.w, v3.y, fmaf(g.z, v2.y, fmaf(g.y, v1.y, g.x * v0.y)));
        v.z = fmaf(g.w, v3.z, fmaf(g.z, v2.z, fmaf(g.y, v1.z, g.x * v0.z)));
        v.w = fmaf(g.w, v3.w, fmaf(g.z, v2.w, fmaf(g.y, v1.w, g.x * v0.w)));

        uint16_t hx, lx, hy, ly, hz, lz, hw_, lw_;
        bf16_split(v.x, hx, lx);
        bf16_split(v.y, hy, ly);
        bf16_split(v.z, hz, lz);
        bf16_split(v.w, hw_, lw_);

        uint32_t uoff = (uint32_t)(pix * 144 + lq * 8);
        *reinterpret_cast<uint2*>(udst + uoff) = make_uint2(pack2(hx, hy), pack2(hz, hw_));
        *reinterpret_cast<uint2*>(udst + UPLANE + uoff) = make_uint2(pack2(lx, ly), pack2(lz, lw_));
    }
}

__global__ __launch_bounds__(256, 2) void mma_main_kernel(float* __restrict__ out) {
    extern __shared__ __align__(128) char smem[];
    uint32_t sb = smem_u32(smem);
    int tid = threadIdx.x;
    int wid = tid >> 5, lane = tid & 31;

    int idx = blockIdx.x;              // 0..255 = b*H + h
    int b = idx >> 7, h = idx & 127;
    int gbase = idx * 128;             // pixel base (full row)

    const float4* xb4 = reinterpret_cast<const float4*>(g_xp) + (size_t)b * HP * WP * 32;

    int wm = (wid & 1) * 64;           // co half
    int wn = (wid >> 1) * 32;          // pixel quarter (32 pix)

    // B ldmx4 lane mapping (covers 2 nt per load)
    uint32_t bBase = (uint32_t)((wn + ((lane >> 4) << 3) + (lane & 7)) * 144 +
                                (((lane >> 3) & 1) << 4));

    // gather mapping: warp owns 16 pixels; half-warp per pixel (16 lanes = 64 ci)
    int gp = wid * 16 + (lane >> 4);
    int lq = lane & 15;

    // A fragment table base for this warp's co-half
    const uint4* wAh0 = g_wAf_hi + ((size_t)(wid & 1) * 4) * 128 + lane;
    const uint4* wAl0 = g_wAf_lo + ((size_t)(wid & 1) * 4) * 128 + lane;

    float acc[4][4][4];
#pragma unroll
    for (int mt = 0; mt < 4; ++mt)
#pragma unroll
        for (int nt = 0; nt < 4; ++nt)
#pragma unroll
            for (int j = 0; j < 4; ++j) acc[mt][nt][j] = 0.f;

    // prologue: gather chunk 0 into buffer 0
    gather_chunk(smem + SMU0, 0, gbase, xb4, gp, lq);
    __syncthreads();

    for (int chunk = 0; chunk < 18; ++chunk) {
        if (chunk < 17)
            gather_chunk(smem + (((chunk + 1) & 1) ? SMU1 : SMU0), chunk + 1, gbase, xb4, gp, lq);

        uint32_t ub = sb + ((chunk & 1) ? SMU1 : SMU0);
        const uint4* wAh = wAh0 + (size_t)chunk * 1024;
        const uint4* wAl = wAl0 + (size_t)chunk * 1024;
#pragma unroll
        for (int ks = 0; ks < 4; ++ks) {
            uint32_t BH[2][4], BL[2][4];
#pragma unroll
            for (int np = 0; np < 2; ++np) {
                uint32_t bo = ub + bBase + (uint32_t)(np * 16 * 144 + ks * 32);
                ldmx4(BH[np], bo);
                ldmx4(BL[np], bo + UPLANE);
            }
#pragma unroll
            for (int mt = 0; mt < 4; ++mt) {
                uint4 ah4 = wAh[(mt * 4 + ks) * 32];
                uint4 al4 = wAl[(mt * 4 + ks) * 32];
                uint32_t AH[4] = {ah4.x, ah4.y, ah4.z, ah4.w};
                uint32_t AL[4] = {al4.x, al4.y, al4.z, al4.w};
#pragma unroll
                for (int np = 0; np < 2; ++np) {
                    mma_bf16(acc[mt][np * 2],     AH, BH[np][0], BH[np][1]);
                    mma_bf16(acc[mt][np * 2],     AL, BH[np][0], BH[np][1]);
                    mma_bf16(acc[mt][np * 2],     AH, BL[np][0], BL[np][1]);
                    mma_bf16(acc[mt][np * 2 + 1], AH, BH[np][2], BH[np][3]);
                    mma_bf16(acc[mt][np * 2 + 1], AL, BH[np][2], BH[np][3]);
                    mma_bf16(acc[mt][np * 2 + 1], AH, BL[np][2], BL[np][3]);
                }
            }
        }
        __syncthreads();
    }

    int g4 = lane >> 2, t4 = lane & 3;
#pragma unroll
    for (int mt = 0; mt < 4; ++mt) {
#pragma unroll
        for (int nt = 0; nt < 4; ++nt) {
            int co = wm + mt * 16 + g4;
            int px = wn + nt * 8 + t4 * 2;
            float* op = out + (((size_t)b * CO + co) * H + h) * W + px;
            *reinterpret_cast<float2*>(op) = make_float2(acc[mt][nt][0], acc[mt][nt][1]);
            float* op2 = out + (((size_t)b * CO + co + 8) * H + h) * W + px;
            *reinterpret_cast<float2*>(op2) = make_float2(acc[mt][nt][2], acc[mt][nt][3]);
        }
    }
}

// ---------------------------------------------------------------------------
extern "C" void kernel_launch(void* const* d_in, const int* in_sizes, int n_in,
                              void* d_out, int out_size) {
    const float* x      = (const float*)d_in[0];
    const float* w_p    = (const float*)d_in[1];
    const float* b_p    = (const float*)d_in[2];
    const float* w_m    = (const float*)d_in[3];
    const float* b_m    = (const float*)d_in[4];
    const float* w_conv = (const float*)d_in[5];
    float* out = (float*)d_out;

    cudaFuncSetAttribute(mma_main_kernel, cudaFuncAttributeMaxDynamicSharedMemorySize, SM_TOTAL);
    cudaFuncSetAttribute(conv_mma_kernel, cudaFuncAttributeMaxDynamicSharedMemorySize, SC_TOTAL);

    zero_border_kernel<<<(B * 516 * 32 + 255) / 256, 256>>>();
    prep_weights_kernel<<<720, 256>>>(w_p, w_m, w_conv);
    pad_transpose_kernel<<<dim3(W / 32, C / 32, B * H), dim3(32, 8)>>>(x);
    conv_mma_kernel<<<512, 256, SC_TOTAL>>>(b_p, b_m);
    mma_main_kernel<<<B * H, 256, SM_TOTAL>>>(out);
}

// round 17
// speedup vs baseline: 1.0286x; 1.0286x over previous
#include <cuda_runtime.h>
#include <cuda_bf16.h>
#include <math.h>
#include <stdint.h>

// Problem constants
#define B 2
#define C 128
#define H 128
#define W 128
#define HP 130
#define WP 130
#define NPT 9
#define CO 128
#define BHW (B * H * W)

// Scratch (device globals; allocation-free)
__device__ __align__(16) float g_xp[B * HP * WP * C];           // padded NHWC x (~17.3 MB)
__device__ __align__(16) float4 g_gates2[NPT * BHW];            // gates [n][pix] (lt,rb,lb,rt)
__device__ __align__(16) int4   g_offs2 [NPT * BHW];            // corner spatial offsets [n][pix]
// Weights pre-packed PER MMA FRAGMENT (uint4 = lane's 4 a-regs, bf16x2 each):
//   main conv:   ((chunk*8 + m16)*4 + ks)*32 + lane   (chunk = tap*2 + half)
//   offset conv: ((chunk*2 + m16)*4 + ks)*32 + lane
__device__ __align__(16) uint4 g_wAf_hi[18 * 8 * 4 * 32];
__device__ __align__(16) uint4 g_wAf_lo[18 * 8 * 4 * 32];
__device__ __align__(16) uint4 g_wOf_hi[18 * 2 * 4 * 32];
__device__ __align__(16) uint4 g_wOf_lo[18 * 2 * 4 * 32];

// ---------------------------------------------------------------------------
// PTX helpers (all sm_80-era: no arch-"a" gated instructions)
__device__ __forceinline__ uint32_t smem_u32(const void* p) {
    uint32_t a;
    asm("{ .reg .u64 t; cvta.to.shared.u64 t, %1; cvt.u32.u64 %0, t; }" : "=r"(a) : "l"(p));
    return a;
}
__device__ __forceinline__ void ldmx4(uint32_t* r, uint32_t a) {
    asm volatile("ldmatrix.sync.aligned.m8n8.x4.shared.b16 {%0,%1,%2,%3}, [%4];"
                 : "=r"(r[0]), "=r"(r[1]), "=r"(r[2]), "=r"(r[3]) : "r"(a));
}
__device__ __forceinline__ void mma_bf16(float* c, const uint32_t* a, uint32_t b0, uint32_t b1) {
    asm volatile(
        "mma.sync.aligned.m16n8k16.row.col.f32.bf16.bf16.f32 "
        "{%0,%1,%2,%3}, {%4,%5,%6,%7}, {%8,%9}, {%0,%1,%2,%3};"
        : "+f"(c[0]), "+f"(c[1]), "+f"(c[2]), "+f"(c[3])
        : "r"(a[0]), "r"(a[1]), "r"(a[2]), "r"(a[3]), "r"(b0), "r"(b1));
}
__device__ __forceinline__ void bf16_split(float v, uint16_t& hi, uint16_t& lo) {
    __nv_bfloat16 h = __float2bfloat16_rn(v);
    __nv_bfloat16 l = __float2bfloat16_rn(v - __bfloat162float(h));
    hi = __bfloat16_as_ushort(h);
    lo = __bfloat16_as_ushort(l);
}
__device__ __forceinline__ uint32_t pack2(uint16_t a, uint16_t b) {
    return (uint32_t)a | ((uint32_t)b << 16);
}

// ---------------------------------------------------------------------------
// Kernel 0: zero only the pad border of g_xp (interior fully overwritten)
__global__ void zero_border_kernel() {
    int i = blockIdx.x * blockDim.x + threadIdx.x;
    if (i >= B * 516 * 32) return;
    int q = i & 31;
    int p = i >> 5;
    int b = p / 516;
    int r = p - b * 516;
    int hh, ww;
    if (r < 130)      { hh = 0;        ww = r; }
    else if (r < 260) { hh = 129;      ww = r - 130; }
    else if (r < 388) { hh = r - 259;  ww = 0; }
    else              { hh = r - 387;  ww = 129; }
    reinterpret_cast<float4*>(g_xp)[((size_t)(b * HP + hh) * WP + ww) * 32 + q] =
        make_float4(0.f, 0.f, 0.f, 0.f);
}

// ---------------------------------------------------------------------------
// Kernel 1: weight re-layouts -> per-fragment packed uint4 (main + offset conv)
__global__ void prep_weights_kernel(const float* __restrict__ wp,
                                    const float* __restrict__ wm,
                                    const float* __restrict__ wc) {
    const int n_of  = 18 * 2 * 4 * 32;       // 4608 offset-conv fragments
    const int n_wa  = 18 * 8 * 4 * 32;       // 18432 main-conv fragments
    for (int e = blockIdx.x * blockDim.x + threadIdx.x; e < n_of + n_wa;
         e += gridDim.x * blockDim.x) {
        if (e < n_of) {
            int chunk = e >> 8;               // tap*2 + half
            int r = e & 255;
            int m16 = r >> 7;
            int r2 = r & 127;
            int ks = r2 >> 5;
            int lane = r2 & 31;
            int g4 = lane >> 2, t4 = lane & 3;
            int tap = chunk >> 1, half = chunk & 1;
            uint32_t hi4[4], lo4[4];
#pragma unroll
            for (int j = 0; j < 4; ++j) {
                int ch = m16 * 16 + g4 + (j & 1) * 8;
                int kk = ks * 16 + t4 * 2 + (j >> 1) * 8;
                int ci = half * 64 + kk;
                float v0 = 0.f, v1 = 0.f;
                if (ch < 18) {
                    v0 = wp[(ch * C + ci) * 9 + tap];
                    v1 = wp[(ch * C + ci + 1) * 9 + tap];
                } else if (ch < 27) {
                    v0 = wm[((ch - 18) * C + ci) * 9 + tap];
                    v1 = wm[((ch - 18) * C + ci + 1) * 9 + tap];
                }
                uint16_t h0, l0, h1, l1;
                bf16_split(v0, h0, l0);
                bf16_split(v1, h1, l1);
                hi4[j] = pack2(h0, h1);
                lo4[j] = pack2(l0, l1);
            }
            g_wOf_hi[e] = make_uint4(hi4[0], hi4[1], hi4[2], hi4[3]);
            g_wOf_lo[e] = make_uint4(lo4[0], lo4[1], lo4[2], lo4[3]);
        } else {
            int t = e - n_of;                 // ((chunk*8+m16)*4+ks)*32+lane
            int chunk = t >> 10;
            int r = t & 1023;
            int m16 = r >> 7;
            int r2 = r & 127;
            int ks = r2 >> 5;
            int lane = r2 & 31;
            int g4 = lane >> 2, t4 = lane & 3;
            int tap = chunk >> 1, half = chunk & 1;
            uint32_t hi4[4], lo4[4];
#pragma unroll
            for (int j = 0; j < 4; ++j) {
                int row = m16 * 16 + g4 + (j & 1) * 8;           // co
                int kk  = ks * 16 + t4 * 2 + (j >> 1) * 8;       // k within chunk
                int ci = half * 64 + kk;
                float v0 = wc[(row * C + ci) * 9 + tap];
                float v1 = wc[(row * C + ci + 1) * 9 + tap];
                uint16_t h0, l0, h1, l1;
                bf16_split(v0, h0, l0);
                bf16_split(v1, h1, l1);
                hi4[j] = pack2(h0, h1);
                lo4[j] = pack2(l0, l1);
            }
            g_wAf_hi[t] = make_uint4(hi4[0], hi4[1], hi4[2], hi4[3]);
            g_wAf_lo[t] = make_uint4(lo4[0], lo4[1], lo4[2], lo4[3]);
        }
    }
}

// ---------------------------------------------------------------------------
// Kernel 2: pad + transpose NCHW -> padded NHWC
__global__ void pad_transpose_kernel(const float* __restrict__ x) {
    __shared__ float tile[32][33];
    int w0 = blockIdx.x * 32;
    int c0 = blockIdx.y * 32;
    int bh = blockIdx.z;
    int b = bh >> 7, h = bh & 127;
    int tx = threadIdx.x, ty = threadIdx.y;
#pragma unroll
    for (int r = 0; r < 4; ++r) {
        int ci = c0 + ty + r * 8;
        tile[ty + r * 8][tx] = x[(((size_t)b * C + ci) * H + h) * W + w0 + tx];
    }
    __syncthreads();
#pragma unroll
    for (int r = 0; r < 4; ++r) {
        int w = w0 + ty + r * 8;
        g_xp[(((size_t)b * HP + h + 1) * WP + (w + 1)) * C + c0 + tx] = tile[tx][ty + r * 8];
    }
}

// ---------------------------------------------------------------------------
// Kernel 3: offset/mask conv via HMMA, A-fragments direct from L2 (no W smem),
// per-tap BATCHED fragment loads (MLP 8) so L2 latency hides under MMAs.
// Per ci-half: stage U once, then 9 taps x 4 k-steps, ZERO barriers inside.
// CTA = 27(32) ch x 64 pixels, 256 thr, 57 KB smem. FUSED gate/index epilogue.
#define SC_UROW (66 * 144)              // 9504 B per xp row
#define SC_UHI 0                        // 3 rows hi: 28512
#define SC_ULO (3 * SC_UROW)            // 3 rows lo: 28512
#define SC_TOTAL (6 * SC_UROW)          // 57024 B
__global__ __launch_bounds__(256, 2) void conv_mma_kernel(const float* __restrict__ bp,
                                                          const float* __restrict__ bm) {
    extern __shared__ __align__(128) char smem[];
    uint32_t sb = smem_u32(smem);
    int tid = threadIdx.x;
    int wid = tid >> 5, lane = tid & 31;

    int idx = blockIdx.x;
    int b = idx >> 8;
    int h = (idx >> 1) & 127;
    int w0 = (idx & 1) * 64;

    const float4* xb4 = reinterpret_cast<const float4*>(g_xp) + (size_t)b * HP * WP * 32;

    int wm = (wid & 1) * 16;          // ch half (m16 tile)
    int wn = (wid >> 1) * 16;         // pixel quarter

    int bRow = wn + ((lane >> 4) << 3) + (lane & 7);
    uint32_t bKoff = (uint32_t)(((lane >> 3) & 1) << 4);

    // A fragment table base for this warp's m16 tile
    const uint4* wOh0 = g_wOf_hi + (size_t)(wid & 1) * 128 + lane;
    const uint4* wOl0 = g_wOf_lo + (size_t)(wid & 1) * 128 + lane;

    float acc[2][4];
#pragma unroll
    for (int nt = 0; nt < 2; ++nt)
#pragma unroll
        for (int j = 0; j < 4; ++j) acc[nt][j] = 0.f;

    for (int half = 0; half < 2; ++half) {
        __syncthreads();   // previous half's MMAs done; U reusable

        // stage U: 3 rows x 66 pixels x 16 float4, hi/lo split
        for (int i = tid; i < 3 * 66 * 16; i += 256) {
            int row = i / (66 * 16);
            int rem = i - row * (66 * 16);
            int pix = rem >> 4;
            int q = rem & 15;
            float4 v = xb4[((size_t)(h + row) * WP + (w0 + pix)) * 32 + half * 16 + q];
            uint16_t hx, lx, hy, ly, hz, lz, hw_, lw_;
            bf16_split(v.x, hx, lx);
            bf16_split(v.y, hy, ly);
            bf16_split(v.z, hz, lz);
            bf16_split(v.w, hw_, lw_);
            uint32_t uoff = (uint32_t)(row * SC_UROW + pix * 144 + q * 8);
            *reinterpret_cast<uint2*>(smem + SC_UHI + uoff) = make_uint2(pack2(hx, hy), pack2(hz, hw_));
            *reinterpret_cast<uint2*>(smem + SC_ULO + uoff) = make_uint2(pack2(lx, ly), pack2(lz, lw_));
        }
        __syncthreads();

        // 9 taps x 4 k-steps, no barriers; A fragments batched per tap from L2
#pragma unroll
        for (int tap = 0; tap < 9; ++tap) {
            int dh = tap / 3, dw = tap - dh * 3;
            int chunk = tap * 2 + half;
            const uint4* wOh = wOh0 + (size_t)chunk * 256;
            const uint4* wOl = wOl0 + (size_t)chunk * 256;
            uint32_t ubase = (uint32_t)(dh * SC_UROW) + (uint32_t)(bRow + dw) * 144 + bKoff;

            // batch all 8 fragment loads for this tap (MLP 8)
            uint4 AH4[4], AL4[4];
#pragma unroll
            for (int ks = 0; ks < 4; ++ks) {
                AH4[ks] = wOh[ks * 32];
                AL4[ks] = wOl[ks * 32];
            }
#pragma unroll
            for (int ks = 0; ks < 4; ++ks) {
                uint32_t AH[4] = {AH4[ks].x, AH4[ks].y, AH4[ks].z, AH4[ks].w};
                uint32_t AL[4] = {AL4[ks].x, AL4[ks].y, AL4[ks].z, AL4[ks].w};
                uint32_t bo = ubase + (uint32_t)(ks * 32);
                uint32_t BH[4], BL[4];
                ldmx4(BH, sb + SC_UHI + bo);
                ldmx4(BL, sb + SC_ULO + bo);
                mma_bf16(acc[0], AH, BH[0], BH[1]);
                mma_bf16(acc[0], AL, BH[0], BH[1]);
                mma_bf16(acc[0], AH, BL[0], BL[1]);
                mma_bf16(acc[1], AH, BH[2], BH[3]);
                mma_bf16(acc[1], AL, BH[2], BH[3]);
                mma_bf16(acc[1], AH, BL[2], BL[3]);
            }
        }
    }

    // ---- fused epilogue: exchange acc through smem, compute gates/offs ----
    __syncthreads();
    float* sacc = reinterpret_cast<float*>(smem);   // [32 ch][64 pix]
    {
        int g4 = lane >> 2, t4 = lane & 3;
#pragma unroll
        for (int nt = 0; nt < 2; ++nt) {
            int px = wn + nt * 8 + t4 * 2;
            int ch = wm + g4;
            *reinterpret_cast<float2*>(&sacc[ch * 64 + px]) = make_float2(acc[nt][0], acc[nt][1]);
            *reinterpret_cast<float2*>(&sacc[(ch + 8) * 64 + px]) = make_float2(acc[nt][2], acc[nt][3]);
        }
    }
    __syncthreads();

    int gpix0 = (b * H + h) * W + w0;
    for (int i = tid; i < 64 * NPT; i += 256) {
        int pix = i & 63;
        int n = i >> 6;
        float ox = sacc[n * 64 + pix]        + bp[n];
        float oy = sacc[(9 + n) * 64 + pix]  + bp[9 + n];
        float mr = sacc[(18 + n) * 64 + pix] + bm[n];
        float m = 1.f / (1.f + expf(-mr));
        float px = ox + (float)(h + 1) + (float)(n / 3 - 1);
        float py = oy + (float)(w0 + pix + 1) + (float)(n % 3 - 1);
        float fx = floorf(px), fy = floorf(py);
        float qltx = fminf(fmaxf(fx,       0.f), 129.f);
        float qlty = fminf(fmaxf(fy,       0.f), 129.f);
        float qrbx = fminf(fmaxf(fx + 1.f, 0.f), 129.f);
        float qrby = fminf(fmaxf(fy + 1.f, 0.f), 129.f);
        float pxc = fminf(fmaxf(px, 0.f), 129.f);
        float pyc = fminf(fmaxf(py, 0.f), 129.f);
        float ax = 1.f + (qltx - pxc);
        float bx = 1.f - (qrbx - pxc);
        float ay = 1.f + (qlty - pyc);
        float by = 1.f - (qrby - pyc);
        int ilt_x = (int)qltx, ilt_y = (int)qlty;
        int irb_x = (int)qrbx, irb_y = (int)qrby;
        g_gates2[n * BHW + gpix0 + pix] = make_float4(ax * ay * m, bx * by * m, ax * by * m, bx * ay * m);
        g_offs2 [n * BHW + gpix0 + pix] = make_int4(ilt_x * WP + ilt_y, irb_x * WP + irb_y,
                                                    ilt_x * WP + irb_y, irb_x * WP + ilt_y);
    }
}

// ---------------------------------------------------------------------------
// Kernel 4: fused gather + bf16-split GEMM; A-fragments direct from L2.
// CTA = 128 co x 128 pixels, 256 thr (8 warps, 2M x 4N), 2 CTAs/SM.
// K = 1152 as 18 chunks of 64. U double-buffered (73.7 KB); ONE barrier/chunk.
#define SMU0 0
#define SMU1 36864
#define UPLANE 18432                  // lo plane offset within a U buffer
#define SM_TOTAL 73728

__device__ __forceinline__ void gather_chunk(char* udst, int chunk, int gbase,
                                             const float4* xb4, int gp, int lq) {
    int tap = chunk >> 1, half = chunk & 1;
    const float4* xh = xb4 + half * 16;
    const float4* gg = g_gates2 + (size_t)tap * BHW + gbase;
    const int4*  go = g_offs2  + (size_t)tap * BHW + gbase;
#pragma unroll
    for (int pp = 0; pp < 8; ++pp) {
        int pix = gp + pp * 2;
        float4 g = gg[pix];
        int4  o = go[pix];
        float4 v0 = xh[(size_t)o.x * 32 + lq];
        float4 v1 = xh[(size_t)o.y * 32 + lq];
        float4 v2 = xh[(size_t)o.z * 32 + lq];
        float4 v3 = xh[(size_t)o.w * 32 + lq];
        float4 v;
        v.x = fmaf(g.w, v3.x, fmaf(g.z, v2.x, fmaf(g.y, v1.x, g.x * v0.x)));
        v.y = fmaf(g.w, v3.y, fmaf(g.z, v2.y, fmaf(g.y, v1.y, g.x * v0.y)));
        v.z = fmaf(g.w, v3.z, fmaf(g.z, v2.z, fmaf(g.y, v1.z, g.x * v0.z)));
        v.w = fmaf(g.w, v3.w, fmaf(g.z, v2.w, fmaf(g.y, v1.w, g.x * v0.w)));

        uint16_t hx, lx, hy, ly, hz, lz, hw_, lw_;
        bf16_split(v.x, hx, lx);
        bf16_split(v.y, hy, ly);
        bf16_split(v.z, hz, lz);
        bf16_split(v.w, hw_, lw_);

        uint32_t uoff = (uint32_t)(pix * 144 + lq * 8);
        *reinterpret_cast<uint2*>(udst + uoff) = make_uint2(pack2(hx, hy), pack2(hz, hw_));
        *reinterpret_cast<uint2*>(udst + UPLANE + uoff) = make_uint2(pack2(lx, ly), pack2(lz, lw_));
    }
}

__global__ __launch_bounds__(256, 2) void mma_main_kernel(float* __restrict__ out) {
    extern __shared__ __align__(128) char smem[];
    uint32_t sb = smem_u32(smem);
    int tid = threadIdx.x;
    int wid = tid >> 5, lane = tid & 31;

    int idx = blockIdx.x;              // 0..255 = b*H + h
    int b = idx >> 7, h = idx & 127;
    int gbase = idx * 128;             // pixel base (full row)

    const float4* xb4 = reinterpret_cast<const float4*>(g_xp) + (size_t)b * HP * WP * 32;

    int wm = (wid & 1) * 64;           // co half
    int wn = (wid >> 1) * 32;          // pixel quarter (32 pix)

    // B ldmx4 lane mapping (covers 2 nt per load)
    uint32_t bBase = (uint32_t)((wn + ((lane >> 4) << 3) + (lane & 7)) * 144 +
                                (((lane >> 3) & 1) << 4));

    // gather mapping: warp owns 16 pixels; half-warp per pixel (16 lanes = 64 ci)
    int gp = wid * 16 + (lane >> 4);
    int lq = lane & 15;

    // A fragment table base for this warp's co-half
    const uint4* wAh0 = g_wAf_hi + ((size_t)(wid & 1) * 4) * 128 + lane;
    const uint4* wAl0 = g_wAf_lo + ((size_t)(wid & 1) * 4) * 128 + lane;

    float acc[4][4][4];
#pragma unroll
    for (int mt = 0; mt < 4; ++mt)
#pragma unroll
        for (int nt = 0; nt < 4; ++nt)
#pragma unroll
            for (int j = 0; j < 4; ++j) acc[mt][nt][j] = 0.f;

    // prologue: gather chunk 0 into buffer 0
    gather_chunk(smem + SMU0, 0, gbase, xb4, gp, lq);
    __syncthreads();

    for (int chunk = 0; chunk < 18; ++chunk) {
        if (chunk < 17)
            gather_chunk(smem + (((chunk + 1) & 1) ? SMU1 : SMU0), chunk + 1, gbase, xb4, gp, lq);

        uint32_t ub = sb + ((chunk & 1) ? SMU1 : SMU0);
        const uint4* wAh = wAh0 + (size_t)chunk * 1024;
        const uint4* wAl = wAl0 + (size_t)chunk * 1024;
#pragma unroll
        for (int ks = 0; ks < 4; ++ks) {
            uint32_t BH[2][4], BL[2][4];
#pragma unroll
            for (int np = 0; np < 2; ++np) {
                uint32_t bo = ub + bBase + (uint32_t)(np * 16 * 144 + ks * 32);
                ldmx4(BH[np], bo);
                ldmx4(BL[np], bo + UPLANE);
            }
#pragma unroll
            for (int mt = 0; mt < 4; ++mt) {
                uint4 ah4 = wAh[(mt * 4 + ks) * 32];
                uint4 al4 = wAl[(mt * 4 + ks) * 32];
                uint32_t AH[4] = {ah4.x, ah4.y, ah4.z, ah4.w};
                uint32_t AL[4] = {al4.x, al4.y, al4.z, al4.w};
#pragma unroll
                for (int np = 0; np < 2; ++np) {
                    mma_bf16(acc[mt][np * 2],     AH, BH[np][0], BH[np][1]);
                    mma_bf16(acc[mt][np * 2],     AL, BH[np][0], BH[np][1]);
                    mma_bf16(acc[mt][np * 2],     AH, BL[np][0], BL[np][1]);
                    mma_bf16(acc[mt][np * 2 + 1], AH, BH[np][2], BH[np][3]);
                    mma_bf16(acc[mt][np * 2 + 1], AL, BH[np][2], BH[np][3]);
                    mma_bf16(acc[mt][np * 2 + 1], AH, BL[np][2], BL[np][3]);
                }
            }
        }
        __syncthreads();
    }

    int g4 = lane >> 2, t4 = lane & 3;
#pragma unroll
    for (int mt = 0; mt < 4; ++mt) {
#pragma unroll
        for (int nt = 0; nt < 4; ++nt) {
            int co = wm + mt * 16 + g4;
            int px = wn + nt * 8 + t4 * 2;
            float* op = out + (((size_t)b * CO + co) * H + h) * W + px;
            *reinterpret_cast<float2*>(op) = make_float2(acc[mt][nt][0], acc[mt][nt][1]);
            float* op2 = out + (((size_t)b * CO + co + 8) * H + h) * W + px;
            *reinterpret_cast<float2*>(op2) = make_float2(acc[mt][nt][2], acc[mt][nt][3]);
        }
    }
}

// ---------------------------------------------------------------------------
extern "C" void kernel_launch(void* const* d_in, const int* in_sizes, int n_in,
                              void* d_out, int out_size) {
    const float* x      = (const float*)d_in[0];
    const float* w_p    = (const float*)d_in[1];
    const float* b_p    = (const float*)d_in[2];
    const float* w_m    = (const float*)d_in[3];
    const float* b_m    = (const float*)d_in[4];
    const float* w_conv = (const float*)d_in[5];
    float* out = (float*)d_out;

    cudaFuncSetAttribute(mma_main_kernel, cudaFuncAttributeMaxDynamicSharedMemorySize, SM_TOTAL);
    cudaFuncSetAttribute(conv_mma_kernel, cudaFuncAttributeMaxDynamicSharedMemorySize, SC_TOTAL);

    zero_border_kernel<<<(B * 516 * 32 + 255) / 256, 256>>>();
    prep_weights_kernel<<<720, 256>>>(w_p, w_m, w_conv);
    pad_transpose_kernel<<<dim3(W / 32, C / 32, B * H), dim3(32, 8)>>>(x);
    conv_mma_kernel<<<512, 256, SC_TOTAL>>>(b_p, b_m);
    mma_main_kernel<<<B * H, 256, SM_TOTAL>>>(out);
}